// round 12
// baseline (speedup 1.0000x reference)
#include <cuda_runtime.h>
#include <cuda_bf16.h>
#include <math.h>

// Problem constants
#define BATCH 4
#define NN 4096
#define DD 256
#define PP 64
#define ALPHA 0.2f
#define KCAP 255

#define NMAIN      (BATCH * 256)          // 1024 main blocks
#define MAIN_BASE  BATCH                  // 4
#define MLP_BASE   (MAIN_BASE + NMAIN)    // 1028
#define FIN_BASE   (MLP_BASE + BATCH * 8) // 1060
#define GRID_SZ    (FIN_BASE + BATCH)     // 1064

// Scratch + handshake flags (no cudaMalloc allowed; zero-init at load,
// finalize resets flags each run for graph-replay determinism)
__device__ float g_v[BATCH][DD];
__device__ float g_hp[BATCH][8][128];
__device__ int   g_flag_v[BATCH];
__device__ int   g_done[BATCH];
__device__ int   g_mlp_done[BATCH];

// NOTE: every array that is cast to float4 is 16-byte aligned BY LAYOUT:
// vector-cast arrays first (sizes are multiples of 16 bytes), scalars last.
struct SmemSetup {
    alignas(16) float x[DD];        // offset 0
    alignas(16) float q[PP];        // offset 1024
    alignas(16) float qpart[8][PP]; // offset 1280
    int seed;                       // trailing scalar
};
struct SmemMain {
    alignas(16) float cm[NN];       // offset 0
    alignas(16) float v[DD];        // offset 16384
};
struct SmemMlp {
    alignas(16) float hp[4][128];
};
struct SmemFin {
    alignas(16) unsigned long long key[NN];  // 32 KB, offset 0
    float h[128];
    float part[16];
    float theta;
    int   hist[256];
    int   wsum[8];
    int   cnt;
    unsigned long long prefix;
    int   k;
};
union SmemU {
    SmemSetup s;
    SmemMain  m;
    SmemMlp   p;
    SmemFin   f;
};

__global__ void __launch_bounds__(512) fused_kernel(
        const float* __restrict__ x,
        const float* __restrict__ adj,
        const float* __restrict__ cmask,
        const float* __restrict__ candmask,
        const float* __restrict__ seed_ctx,
        const float* __restrict__ local_stats,
        const float* __restrict__ Wq,
        const float* __restrict__ Wk,
        const float* __restrict__ w1,
        const float* __restrict__ b1,
        const float* __restrict__ w2,
        const float* __restrict__ b2,
        float* __restrict__ out)
{
    __shared__ __align__(16) SmemU su;
    const int bid = blockIdx.x;
    const int t   = threadIdx.x;

    // =====================================================================
    // Role 1: setup blocks — seed -> q -> v, then release g_flag_v[b]
    // =====================================================================
    if (bid < MAIN_BASE) {
        const int b    = bid;
        const int lane = t & 31;
        if (t == 0) su.s.seed = NN;
        __syncthreads();

        {   // first index with cmask > 0.5
            int lm = NN;
            #pragma unroll
            for (int j = 7; j >= 0; j--) {
                int i = j * 512 + t;
                if (cmask[(size_t)b * NN + i] > 0.5f) lm = i;
            }
            #pragma unroll
            for (int o = 16; o > 0; o >>= 1)
                lm = min(lm, __shfl_xor_sync(0xffffffffu, lm, o));
            if (lane == 0 && lm < NN) atomicMin(&su.s.seed, lm);
        }
        __syncthreads();
        const int seed = (su.s.seed < NN) ? su.s.seed : 0;

        if (t < DD) su.s.x[t] = x[((size_t)b * NN + seed) * DD + t];
        __syncthreads();

        {   // q[p] = sum_d x_seed[d] * Wq[d,p] : 8 chunks x 64 p, 32 each
            const int p = t & 63;
            const int c = t >> 6;
            float acc = 0.f;
            #pragma unroll 8
            for (int dd = 0; dd < 32; dd++) {
                int d = c * 32 + dd;
                acc += su.s.x[d] * Wq[d * PP + p];
            }
            su.s.qpart[c][p] = acc;
        }
        __syncthreads();
        if (t < PP) {
            float a = 0.f;
            #pragma unroll
            for (int c = 0; c < 8; c++) a += su.s.qpart[c][t];
            su.s.q[t] = a;
        }
        __syncthreads();

        {   // v[d] = (Wk[d,:] . q) / 8 : 2 lanes per row, 8 float4 each
            const int d = t >> 1;
            const int j = t & 1;
            const float4* wk4 = (const float4*)(Wk + d * PP + j * 32);
            const float4* q4  = (const float4*)(su.s.q + j * 32);
            float a = 0.f;
            #pragma unroll
            for (int k = 0; k < 8; k++) {
                float4 wv = wk4[k];
                float4 qv = q4[k];
                a += wv.x * qv.x + wv.y * qv.y + wv.z * qv.z + wv.w * qv.w;
            }
            a += __shfl_xor_sync(0xffffffffu, a, 1);
            if (j == 0) g_v[b][d] = a * 0.125f;
        }
        __syncthreads();
        if (t == 0) { __threadfence(); atomicExch(&g_flag_v[b], 1); }
        return;
    }

    // =====================================================================
    // Role 3: theta-MLP partial blocks
    // =====================================================================
    if (bid >= MLP_BASE && bid < FIN_BASE) {
        const int m       = bid - MLP_BASE;
        const int b       = m >> 3;
        const int chunk   = m & 7;
        const int h       = t & 127;
        const int quarter = t >> 7;          // 0..3, 16 inputs each
        float a = 0.f;
        #pragma unroll
        for (int ii = 0; ii < 16; ii++) {
            int g = chunk * 64 + quarter * 16 + ii;
            float inv = (g < 384) ? seed_ctx[(size_t)b * 384 + g]
                                  : local_stats[(size_t)b * 128 + (g - 384)];
            a += inv * w1[g * 128 + h];
        }
        su.p.hp[quarter][h] = a;
        __syncthreads();
        if (t < 128)
            g_hp[b][chunk][t] = (su.p.hp[0][t] + su.p.hp[1][t])
                              + (su.p.hp[2][t] + su.p.hp[3][t]);
        __syncthreads();
        if (t == 0) { __threadfence(); atomicAdd(&g_mlp_done[b], 1); }
        return;
    }

    // =====================================================================
    // Role 2: main streaming blocks (adj first, v late via flag spin)
    // =====================================================================
    if (bid < MLP_BASE) {
        const int m   = bid - MAIN_BASE;
        const int b   = m >> 8;
        const int blk = m & 255;
        float* out_score = out + BATCH * NN;

        {
            const float4* cm4 = (const float4*)(cmask + (size_t)b * NN);
            float4* s4 = (float4*)su.m.cm;
            #pragma unroll
            for (int i = t; i < NN / 4; i += 512) s4[i] = cm4[i];
        }
        __syncthreads();

        const int w    = t >> 5;
        const int lane = t & 31;
        const int n    = (blk << 4) + w;

        const float4* a4 = (const float4*)(adj + ((size_t)b * NN + n) * NN);
        const float4* c4 = (const float4*)su.m.cm;

        float e2c = 0.f, deg = 0.f;
        #pragma unroll 8
        for (int i = lane; i < NN / 4; i += 32) {
            float4 a = a4[i];
            float4 c = c4[i];
            deg += (a.x + a.y) + (a.z + a.w);
            e2c += a.x * c.x + a.y * c.y + a.z * c.z + a.w * c.w;
        }

        // ---- acquire v (setup long finished by now) ----
        if (t == 0) { while (atomicAdd(&g_flag_v[b], 0) == 0) { } }
        __syncthreads();
        __threadfence();
        if (t < DD) su.m.v[t] = __ldcg(&g_v[b][t]);
        __syncthreads();

        float sc = 0.f;
        const float4* x4 = (const float4*)(x + ((size_t)b * NN + n) * DD);
        const float4* v4 = (const float4*)su.m.v;
        #pragma unroll
        for (int i = lane; i < DD / 4; i += 32) {
            float4 xv = x4[i];
            float4 vv = v4[i];
            sc += xv.x * vv.x + xv.y * vv.y + xv.z * vv.z + xv.w * vv.w;
        }

        #pragma unroll
        for (int o = 16; o > 0; o >>= 1) {
            e2c += __shfl_xor_sync(0xffffffffu, e2c, o);
            deg += __shfl_xor_sync(0xffffffffu, deg, o);
            sc  += __shfl_xor_sync(0xffffffffu, sc,  o);
        }

        if (lane == 0) {
            deg = fmaxf(deg, 1.0f);
            out_score[(size_t)b * NN + n] = sc + ALPHA * (e2c / deg);
        }
        __syncthreads();
        if (t == 0) { __threadfence(); atomicAdd(&g_done[b], 1); }
        return;
    }

    // =====================================================================
    // Role 4: finalize blocks (scheduled last; spin until batch complete)
    // =====================================================================
    {
        const int b = bid - FIN_BASE;
        float* out_hard = out;
        float* out_p    = out + BATCH * NN;   // raw scores on entry

        if (t == 0) {
            while (atomicAdd(&g_done[b], 0) < 256)   __nanosleep(128);
            while (atomicAdd(&g_mlp_done[b], 0) < 8) __nanosleep(64);
        }
        __syncthreads();
        __threadfence();

        if (t == 0) { su.f.cnt = 0; su.f.prefix = 0ULL; su.f.k = KCAP; }

        // theta = relu(sum partials + b1) . w2 + b2
        if (t < 128) {
            float a = b1[t];
            #pragma unroll
            for (int c = 0; c < 8; c++) a += __ldcg(&g_hp[b][c][t]);
            su.f.h[t] = fmaxf(a, 0.f) * w2[t];
        }
        __syncthreads();
        if (t < 32) {
            float a = su.f.h[t] + su.f.h[t + 32] + su.f.h[t + 64] + su.f.h[t + 96];
            #pragma unroll
            for (int o = 16; o > 0; o >>= 1) a += __shfl_xor_sync(0xffffffffu, a, o);
            if (t == 0) su.f.theta = a + b2[0];
        }
        __syncthreads();
        const float theta = su.f.theta;

        // p, keys, count(p>0.5) — 8 elements per thread
        int cnt = 0;
        #pragma unroll
        for (int j = 0; j < 8; j++) {
            int i = j * 512 + t;
            float sc = __ldcg(&out_p[(size_t)b * NN + i]);
            float p = 1.0f / (1.0f + expf(-(sc - theta)));
            p *= candmask[(size_t)b * NN + i];
            su.f.key[i] = ((unsigned long long)__float_as_uint(p) << 32)
                        | (unsigned int)(~i);
            cnt += (p > 0.5f) ? 1 : 0;
        }
        #pragma unroll
        for (int o = 16; o > 0; o >>= 1) cnt += __shfl_xor_sync(0xffffffffu, cnt, o);
        if ((t & 31) == 0) atomicAdd(&su.f.cnt, cnt);
        __syncthreads();

        const bool trim = (su.f.cnt > KCAP);
        if (trim) {
            for (int round = 0; round < 8; round++) {
                const int shift = 56 - 8 * round;
                const int kreg = su.f.k;
                const unsigned long long prefix = su.f.prefix;
                if (t < 256) su.f.hist[t] = 0;
                __syncthreads();
                const int hshift = shift + 8;
                #pragma unroll
                for (int j = 0; j < 8; j++) {
                    unsigned long long key = su.f.key[j * 512 + t];
                    bool match = (round == 0) ||
                                 ((key >> hshift) == (prefix >> hshift));
                    if (match) atomicAdd(&su.f.hist[(int)((key >> shift) & 255ULL)], 1);
                }
                __syncthreads();
                int h = 0, Sloc = 0;
                if (t < 256) {
                    h = su.f.hist[t];
                    Sloc = h;
                    const int l = t & 31;
                    #pragma unroll
                    for (int o = 1; o < 32; o <<= 1) {
                        int v = __shfl_down_sync(0xffffffffu, Sloc, o);
                        if (l + o < 32) Sloc += v;
                    }
                    if (l == 0) su.f.wsum[t >> 5] = Sloc;
                }
                __syncthreads();
                if (t < 256) {
                    int S = Sloc;
                    for (int wi = (t >> 5) + 1; wi < 8; wi++) S += su.f.wsum[wi];
                    if (S >= kreg && (S - h) < kreg) {     // unique winner bin
                        su.f.k = kreg - (S - h);
                        su.f.prefix = prefix | ((unsigned long long)t << shift);
                    }
                }
                __syncthreads();
            }
        }
        const unsigned long long kth = trim ? su.f.prefix : 0ULL;

        // write outputs + trimmed sum (deterministic tree reduce)
        float lsum = 0.f;
        #pragma unroll
        for (int j = 0; j < 8; j++) {
            int i = j * 512 + t;
            unsigned long long key = su.f.key[i];
            float p = __uint_as_float((unsigned int)(key >> 32));
            if (key < kth) p = 0.f;
            out_p[(size_t)b * NN + i]    = p;
            out_hard[(size_t)b * NN + i] = (p > 0.5f) ? 1.0f : 0.0f;
            lsum += p;
        }
        #pragma unroll
        for (int o = 16; o > 0; o >>= 1) lsum += __shfl_xor_sync(0xffffffffu, lsum, o);
        if ((t & 31) == 0) su.f.part[t >> 5] = lsum;
        __syncthreads();
        if (t < 32) {
            float a = (t < 16) ? su.f.part[t] : 0.f;
            #pragma unroll
            for (int o = 16; o > 0; o >>= 1) a += __shfl_xor_sync(0xffffffffu, a, o);
            if (t == 0) {
                float* tail = out + 2 * BATCH * NN;
                tail[b]             = theta;
                tail[BATCH + b]     = a;
                tail[2 * BATCH + b] = a * (1.0f / (float)NN);
            }
        }
        __syncthreads();
        // reset flags for next graph replay (deterministic across replays)
        if (t == 0) {
            atomicExch(&g_flag_v[b], 0);
            atomicExch(&g_done[b], 0);
            atomicExch(&g_mlp_done[b], 0);
        }
    }
}

// ---------------------------------------------------------------------------
extern "C" void kernel_launch(void* const* d_in, const int* in_sizes, int n_in,
                              void* d_out, int out_size)
{
    const float* x           = (const float*)d_in[0];
    const float* adj         = (const float*)d_in[1];
    const float* seed_ctx    = (const float*)d_in[2];
    const float* local_stats = (const float*)d_in[3];
    const float* cmask       = (const float*)d_in[4];
    const float* candmask    = (const float*)d_in[5];
    const float* Wq          = (const float*)d_in[6];
    const float* Wk          = (const float*)d_in[7];
    const float* w1          = (const float*)d_in[8];
    const float* b1          = (const float*)d_in[9];
    const float* w2          = (const float*)d_in[10];
    const float* b2          = (const float*)d_in[11];
    float* out = (float*)d_out;

    fused_kernel<<<GRID_SZ, 512>>>(x, adj, cmask, candmask, seed_ctx,
                                   local_stats, Wq, Wk, w1, b1, w2, b2, out);
}

// round 15
// speedup vs baseline: 1.0233x; 1.0233x over previous
#include <cuda_runtime.h>
#include <cuda_bf16.h>
#include <math.h>

// Problem constants
#define BATCH 4
#define NN 4096
#define DD 256
#define PP 64
#define ALPHA 0.2f
#define KCAP 255

#define NMAIN      (BATCH * 256)          // 1024 main blocks
#define MAIN_BASE  BATCH                  // 4
#define MLP_BASE   (MAIN_BASE + NMAIN)    // 1028
#define FIN_BASE   (MLP_BASE + BATCH * 8) // 1060
#define GRID_SZ    (FIN_BASE + BATCH)     // 1064

// Scratch + handshake flags (no cudaMalloc allowed; zero-init at load,
// finalize resets flags each run for graph-replay determinism)
__device__ float g_v[BATCH][DD];
__device__ float g_hp[BATCH][8][128];
__device__ int   g_flag_v[BATCH];
__device__ int   g_done[BATCH];
__device__ int   g_mlp_done[BATCH];

// NOTE: every array that is cast to float4 is 16-byte aligned BY LAYOUT:
// vector-cast arrays first (sizes are multiples of 16 bytes), scalars last.
struct SmemSetup {
    alignas(16) float x[DD];        // offset 0
    alignas(16) float q[PP];        // offset 1024
    alignas(16) float qpart[8][PP]; // offset 1280
    int seed;                       // trailing scalar
};
struct SmemMain {
    alignas(16) float cm[NN];       // offset 0
    alignas(16) float v[DD];        // offset 16384
};
struct SmemMlp {
    alignas(16) float hp[4][128];
};
struct SmemFin {
    alignas(16) unsigned long long key[NN];  // 32 KB, offset 0
    float h[128];
    float part[16];
    float theta;
    int   hist[256];
    int   wsum[8];
    int   cnt;
    unsigned long long prefix;
    int   k;
};
union SmemU {
    SmemSetup s;
    SmemMain  m;
    SmemMlp   p;
    SmemFin   f;
};

// minBlocksPerMP=4 caps regs at 32 -> 4 blocks/SM = 64 warps for the
// DRAM-bound stream (was 3 blocks / 48 warps at 40 regs).
__global__ void __launch_bounds__(512, 4) fused_kernel(
        const float* __restrict__ x,
        const float* __restrict__ adj,
        const float* __restrict__ cmask,
        const float* __restrict__ candmask,
        const float* __restrict__ seed_ctx,
        const float* __restrict__ local_stats,
        const float* __restrict__ Wq,
        const float* __restrict__ Wk,
        const float* __restrict__ w1,
        const float* __restrict__ b1,
        const float* __restrict__ w2,
        const float* __restrict__ b2,
        float* __restrict__ out)
{
    __shared__ __align__(16) SmemU su;
    const int bid = blockIdx.x;
    const int t   = threadIdx.x;

    // =====================================================================
    // Role 1: setup blocks — seed -> q -> v, then release g_flag_v[b]
    // =====================================================================
    if (bid < MAIN_BASE) {
        const int b    = bid;
        const int lane = t & 31;
        if (t == 0) su.s.seed = NN;
        __syncthreads();

        {   // first index with cmask > 0.5
            int lm = NN;
            #pragma unroll
            for (int j = 7; j >= 0; j--) {
                int i = j * 512 + t;
                if (cmask[(size_t)b * NN + i] > 0.5f) lm = i;
            }
            #pragma unroll
            for (int o = 16; o > 0; o >>= 1)
                lm = min(lm, __shfl_xor_sync(0xffffffffu, lm, o));
            if (lane == 0 && lm < NN) atomicMin(&su.s.seed, lm);
        }
        __syncthreads();
        const int seed = (su.s.seed < NN) ? su.s.seed : 0;

        if (t < DD) su.s.x[t] = x[((size_t)b * NN + seed) * DD + t];
        __syncthreads();

        {   // q[p] = sum_d x_seed[d] * Wq[d,p] : 8 chunks x 64 p, 32 each
            const int p = t & 63;
            const int c = t >> 6;
            float acc = 0.f;
            #pragma unroll 8
            for (int dd = 0; dd < 32; dd++) {
                int d = c * 32 + dd;
                acc += su.s.x[d] * Wq[d * PP + p];
            }
            su.s.qpart[c][p] = acc;
        }
        __syncthreads();
        if (t < PP) {
            float a = 0.f;
            #pragma unroll
            for (int c = 0; c < 8; c++) a += su.s.qpart[c][t];
            su.s.q[t] = a;
        }
        __syncthreads();

        {   // v[d] = (Wk[d,:] . q) / 8 : 2 lanes per row, 8 float4 each
            const int d = t >> 1;
            const int j = t & 1;
            const float4* wk4 = (const float4*)(Wk + d * PP + j * 32);
            const float4* q4  = (const float4*)(su.s.q + j * 32);
            float a = 0.f;
            #pragma unroll
            for (int k = 0; k < 8; k++) {
                float4 wv = wk4[k];
                float4 qv = q4[k];
                a += wv.x * qv.x + wv.y * qv.y + wv.z * qv.z + wv.w * qv.w;
            }
            a += __shfl_xor_sync(0xffffffffu, a, 1);
            if (j == 0) g_v[b][d] = a * 0.125f;
        }
        __syncthreads();
        if (t == 0) { __threadfence(); atomicExch(&g_flag_v[b], 1); }
        return;
    }

    // =====================================================================
    // Role 3: theta-MLP partial blocks
    // =====================================================================
    if (bid >= MLP_BASE && bid < FIN_BASE) {
        const int m       = bid - MLP_BASE;
        const int b       = m >> 3;
        const int chunk   = m & 7;
        const int h       = t & 127;
        const int quarter = t >> 7;          // 0..3, 16 inputs each
        float a = 0.f;
        #pragma unroll
        for (int ii = 0; ii < 16; ii++) {
            int g = chunk * 64 + quarter * 16 + ii;
            float inv = (g < 384) ? seed_ctx[(size_t)b * 384 + g]
                                  : local_stats[(size_t)b * 128 + (g - 384)];
            a += inv * w1[g * 128 + h];
        }
        su.p.hp[quarter][h] = a;
        __syncthreads();
        if (t < 128)
            g_hp[b][chunk][t] = (su.p.hp[0][t] + su.p.hp[1][t])
                              + (su.p.hp[2][t] + su.p.hp[3][t]);
        __syncthreads();
        if (t == 0) { __threadfence(); atomicAdd(&g_mlp_done[b], 1); }
        return;
    }

    // =====================================================================
    // Role 2: main streaming blocks (adj first, v late via flag spin)
    // =====================================================================
    if (bid < MLP_BASE) {
        const int m   = bid - MAIN_BASE;
        const int b   = m >> 8;
        const int blk = m & 255;
        float* out_score = out + BATCH * NN;

        {
            const float4* cm4 = (const float4*)(cmask + (size_t)b * NN);
            float4* s4 = (float4*)su.m.cm;
            #pragma unroll
            for (int i = t; i < NN / 4; i += 512) s4[i] = cm4[i];
        }
        __syncthreads();

        const int w    = t >> 5;
        const int lane = t & 31;
        const int n    = (blk << 4) + w;

        const float4* a4 = (const float4*)(adj + ((size_t)b * NN + n) * NN);
        const float4* c4 = (const float4*)su.m.cm;

        float e2c = 0.f, deg = 0.f;
        #pragma unroll 4
        for (int i = lane; i < NN / 4; i += 32) {
            float4 a = a4[i];
            float4 c = c4[i];
            deg += (a.x + a.y) + (a.z + a.w);
            e2c += a.x * c.x + a.y * c.y + a.z * c.z + a.w * c.w;
        }

        // ---- acquire v (setup long finished by now) ----
        if (t == 0) { while (atomicAdd(&g_flag_v[b], 0) == 0) { } }
        __syncthreads();
        __threadfence();
        if (t < DD) su.m.v[t] = __ldcg(&g_v[b][t]);
        __syncthreads();

        float sc = 0.f;
        const float4* x4 = (const float4*)(x + ((size_t)b * NN + n) * DD);
        const float4* v4 = (const float4*)su.m.v;
        #pragma unroll
        for (int i = lane; i < DD / 4; i += 32) {
            float4 xv = x4[i];
            float4 vv = v4[i];
            sc += xv.x * vv.x + xv.y * vv.y + xv.z * vv.z + xv.w * vv.w;
        }

        #pragma unroll
        for (int o = 16; o > 0; o >>= 1) {
            e2c += __shfl_xor_sync(0xffffffffu, e2c, o);
            deg += __shfl_xor_sync(0xffffffffu, deg, o);
            sc  += __shfl_xor_sync(0xffffffffu, sc,  o);
        }

        if (lane == 0) {
            deg = fmaxf(deg, 1.0f);
            out_score[(size_t)b * NN + n] = sc + ALPHA * (e2c / deg);
        }
        __syncthreads();
        if (t == 0) { __threadfence(); atomicAdd(&g_done[b], 1); }
        return;
    }

    // =====================================================================
    // Role 4: finalize blocks (scheduled last; spin until batch complete)
    // =====================================================================
    {
        const int b = bid - FIN_BASE;
        float* out_hard = out;
        float* out_p    = out + BATCH * NN;   // raw scores on entry

        if (t == 0) {
            while (atomicAdd(&g_done[b], 0) < 256)   __nanosleep(128);
            while (atomicAdd(&g_mlp_done[b], 0) < 8) __nanosleep(64);
        }
        __syncthreads();
        __threadfence();

        if (t == 0) { su.f.cnt = 0; su.f.prefix = 0ULL; su.f.k = KCAP; }

        // theta = relu(sum partials + b1) . w2 + b2
        if (t < 128) {
            float a = b1[t];
            #pragma unroll
            for (int c = 0; c < 8; c++) a += __ldcg(&g_hp[b][c][t]);
            su.f.h[t] = fmaxf(a, 0.f) * w2[t];
        }
        __syncthreads();
        if (t < 32) {
            float a = su.f.h[t] + su.f.h[t + 32] + su.f.h[t + 64] + su.f.h[t + 96];
            #pragma unroll
            for (int o = 16; o > 0; o >>= 1) a += __shfl_xor_sync(0xffffffffu, a, o);
            if (t == 0) su.f.theta = a + b2[0];
        }
        __syncthreads();
        const float theta = su.f.theta;

        // p, keys, count(p>0.5) — 8 elements per thread
        int cnt = 0;
        #pragma unroll
        for (int j = 0; j < 8; j++) {
            int i = j * 512 + t;
            float sc = __ldcg(&out_p[(size_t)b * NN + i]);
            float p = 1.0f / (1.0f + expf(-(sc - theta)));
            p *= candmask[(size_t)b * NN + i];
            su.f.key[i] = ((unsigned long long)__float_as_uint(p) << 32)
                        | (unsigned int)(~i);
            cnt += (p > 0.5f) ? 1 : 0;
        }
        #pragma unroll
        for (int o = 16; o > 0; o >>= 1) cnt += __shfl_xor_sync(0xffffffffu, cnt, o);
        if ((t & 31) == 0) atomicAdd(&su.f.cnt, cnt);
        __syncthreads();

        const bool trim = (su.f.cnt > KCAP);
        if (trim) {
            for (int round = 0; round < 8; round++) {
                const int shift = 56 - 8 * round;
                const int kreg = su.f.k;
                const unsigned long long prefix = su.f.prefix;
                if (t < 256) su.f.hist[t] = 0;
                __syncthreads();
                const int hshift = shift + 8;
                #pragma unroll
                for (int j = 0; j < 8; j++) {
                    unsigned long long key = su.f.key[j * 512 + t];
                    bool match = (round == 0) ||
                                 ((key >> hshift) == (prefix >> hshift));
                    if (match) atomicAdd(&su.f.hist[(int)((key >> shift) & 255ULL)], 1);
                }
                __syncthreads();
                int h = 0, Sloc = 0;
                if (t < 256) {
                    h = su.f.hist[t];
                    Sloc = h;
                    const int l = t & 31;
                    #pragma unroll
                    for (int o = 1; o < 32; o <<= 1) {
                        int v = __shfl_down_sync(0xffffffffu, Sloc, o);
                        if (l + o < 32) Sloc += v;
                    }
                    if (l == 0) su.f.wsum[t >> 5] = Sloc;
                }
                __syncthreads();
                if (t < 256) {
                    int S = Sloc;
                    for (int wi = (t >> 5) + 1; wi < 8; wi++) S += su.f.wsum[wi];
                    if (S >= kreg && (S - h) < kreg) {     // unique winner bin
                        su.f.k = kreg - (S - h);
                        su.f.prefix = prefix | ((unsigned long long)t << shift);
                    }
                }
                __syncthreads();
            }
        }
        const unsigned long long kth = trim ? su.f.prefix : 0ULL;

        // write outputs + trimmed sum (deterministic tree reduce)
        float lsum = 0.f;
        #pragma unroll
        for (int j = 0; j < 8; j++) {
            int i = j * 512 + t;
            unsigned long long key = su.f.key[i];
            float p = __uint_as_float((unsigned int)(key >> 32));
            if (key < kth) p = 0.f;
            out_p[(size_t)b * NN + i]    = p;
            out_hard[(size_t)b * NN + i] = (p > 0.5f) ? 1.0f : 0.0f;
            lsum += p;
        }
        #pragma unroll
        for (int o = 16; o > 0; o >>= 1) lsum += __shfl_xor_sync(0xffffffffu, lsum, o);
        if ((t & 31) == 0) su.f.part[t >> 5] = lsum;
        __syncthreads();
        if (t < 32) {
            float a = (t < 16) ? su.f.part[t] : 0.f;
            #pragma unroll
            for (int o = 16; o > 0; o >>= 1) a += __shfl_xor_sync(0xffffffffu, a, o);
            if (t == 0) {
                float* tail = out + 2 * BATCH * NN;
                tail[b]             = theta;
                tail[BATCH + b]     = a;
                tail[2 * BATCH + b] = a * (1.0f / (float)NN);
            }
        }
        __syncthreads();
        // reset flags for next graph replay (deterministic across replays)
        if (t == 0) {
            atomicExch(&g_flag_v[b], 0);
            atomicExch(&g_done[b], 0);
            atomicExch(&g_mlp_done[b], 0);
        }
    }
}

// ---------------------------------------------------------------------------
extern "C" void kernel_launch(void* const* d_in, const int* in_sizes, int n_in,
                              void* d_out, int out_size)
{
    const float* x           = (const float*)d_in[0];
    const float* adj         = (const float*)d_in[1];
    const float* seed_ctx    = (const float*)d_in[2];
    const float* local_stats = (const float*)d_in[3];
    const float* cmask       = (const float*)d_in[4];
    const float* candmask    = (const float*)d_in[5];
    const float* Wq          = (const float*)d_in[6];
    const float* Wk          = (const float*)d_in[7];
    const float* w1          = (const float*)d_in[8];
    const float* b1          = (const float*)d_in[9];
    const float* w2          = (const float*)d_in[10];
    const float* b2          = (const float*)d_in[11];
    float* out = (float*)d_out;

    fused_kernel<<<GRID_SZ, 512>>>(x, adj, cmask, candmask, seed_ctx,
                                   local_stats, Wq, Wk, w1, b1, w2, b2, out);
}